// round 1
// baseline (speedup 1.0000x reference)
#include <cuda_runtime.h>
#include <math.h>

// GJR-GARCH(1,1) recurrence:  h[t] = c[t] + beta*h[t-1],  h[0] = var(returns, ddof=1)
// c[t] = omega + (alpha + gamma*[r[t-1]<0]) * r[t-1]^2   (t >= 1)
// Output: [sqrt(h) (N floats) | h (N floats)]
//
// beta^k underflows relevance within ~150 steps, so the scan is local:
//  - each warp owns a CHUNK=1024 element slice
//  - chunk carry-in = 256-term beta-weighted window over the previous chunk (exact to fp32)
//  - inside the warp: per-lane serial segments (SEG=32) + affine warp scan for lane carries

#define SEG   32
#define CHUNK (SEG * 32)
#define TPB   256
#define NPART 2048
#define WWIN  256   // lookback window terms (beta^256 ~ 3e-19)

__device__ float g_ps[NPART];
__device__ float g_pq[NPART];
__device__ float g_h0;

// ---------------------------------------------------------------------------
// Kernel 1: per-block partial (sum, sumsq) — deterministic (no float atomics)
// ---------------------------------------------------------------------------
__global__ void __launch_bounds__(TPB) k_reduce1(const float* __restrict__ r, int n4)
{
    float s0 = 0.f, s1 = 0.f, s2 = 0.f, s3 = 0.f;
    float q0 = 0.f, q1 = 0.f, q2 = 0.f, q3 = 0.f;
    const float4* r4 = (const float4*)r;
    for (int i = blockIdx.x * TPB + threadIdx.x; i < n4; i += gridDim.x * TPB) {
        float4 v = r4[i];
        s0 += v.x; s1 += v.y; s2 += v.z; s3 += v.w;
        q0 = fmaf(v.x, v.x, q0);
        q1 = fmaf(v.y, v.y, q1);
        q2 = fmaf(v.z, v.z, q2);
        q3 = fmaf(v.w, v.w, q3);
    }
    float s = (s0 + s1) + (s2 + s3);
    float q = (q0 + q1) + (q2 + q3);
    #pragma unroll
    for (int d = 16; d; d >>= 1) {
        s += __shfl_xor_sync(0xffffffffu, s, d);
        q += __shfl_xor_sync(0xffffffffu, q, d);
    }
    __shared__ float ss[TPB / 32], sq[TPB / 32];
    int w = threadIdx.x >> 5, lane = threadIdx.x & 31;
    if (lane == 0) { ss[w] = s; sq[w] = q; }
    __syncthreads();
    if (threadIdx.x == 0) {
        float S = 0.f, Q = 0.f;
        #pragma unroll
        for (int i = 0; i < TPB / 32; i++) { S += ss[i]; Q += sq[i]; }
        g_ps[blockIdx.x] = S;
        g_pq[blockIdx.x] = Q;
    }
}

// ---------------------------------------------------------------------------
// Kernel 2: fold 2048 partials -> h0 = (sumsq - sum^2/n)/(n-1)
// ---------------------------------------------------------------------------
__global__ void __launch_bounds__(TPB) k_reduce2(int n)
{
    __shared__ float ss[TPB], sq[TPB];
    float s = 0.f, q = 0.f;
    for (int i = threadIdx.x; i < NPART; i += TPB) { s += g_ps[i]; q += g_pq[i]; }
    ss[threadIdx.x] = s; sq[threadIdx.x] = q;
    __syncthreads();
    for (int ofs = TPB / 2; ofs; ofs >>= 1) {
        if (threadIdx.x < ofs) {
            ss[threadIdx.x] += ss[threadIdx.x + ofs];
            sq[threadIdx.x] += sq[threadIdx.x + ofs];
        }
        __syncthreads();
    }
    if (threadIdx.x == 0) {
        double S = (double)ss[0], Q = (double)sq[0];
        double var = (Q - S * S / (double)n) / (double)(n - 1);
        g_h0 = (float)var;
    }
}

// ---------------------------------------------------------------------------
// Kernel 3: main windowed-scan GARCH kernel
// ---------------------------------------------------------------------------
__global__ void __launch_bounds__(TPB) k_garch(
    const float* __restrict__ r,
    const float* __restrict__ p_omega, const float* __restrict__ p_alpha,
    const float* __restrict__ p_beta,  const float* __restrict__ p_gamma,
    float* __restrict__ out, int n)
{
    const float omega = __ldg(p_omega);
    const float alpha = __ldg(p_alpha);
    const float beta  = __ldg(p_beta);
    const float gamma = __ldg(p_gamma);
    const float ag = alpha + gamma;
    const float h0 = g_h0;

    const int wgid = (blockIdx.x * TPB + threadIdx.x) >> 5;
    const int lane = threadIdx.x & 31;
    const int base = wgid * CHUNK;
    if (base >= n) return;                 // whole warps exit together
    const int a = base + lane * SEG;       // this lane's segment start (output index)

    // beta powers by exact squaring
    const float b2 = beta * beta, b4 = b2 * b2, b8 = b4 * b4, b16 = b8 * b8;
    const float m = b16 * b16;             // beta^SEG = beta^32

    // ---- chunk carry-in: Hw ~= h[base-1] via WWIN-term weighted window ----
    float Hw = 0.f;
    if (base > 0) {
        const int p = base - 1;            // h-index of carry
        float bj = __powf(b8, (float)lane);    // beta^{8*lane}
        float P = 0.f;
        const float* rb = r + (p - 1 - 8 * lane);  // r index for j = 8*lane
        #pragma unroll
        for (int i = 0; i < WWIN / 32; i++) {      // 8 terms per lane
            float rp = rb[-i];
            float coef = (rp < 0.f) ? ag : alpha;
            P = fmaf(bj, fmaf(coef * rp, rp, omega), P);
            bj *= beta;
        }
        #pragma unroll
        for (int d = 16; d; d >>= 1) P += __shfl_xor_sync(0xffffffffu, P, d);
        Hw = P;
    }

    // ---- load this lane's r segment, transform in place to c[] ----
    float c[SEG];
    const bool full = (base + CHUNK <= n);
    if (full) {
        const float4* rv4 = (const float4*)(r + a);
        #pragma unroll
        for (int k4 = 0; k4 < SEG / 4; k4++) {
            float4 v = rv4[k4];
            c[4 * k4 + 0] = v.x; c[4 * k4 + 1] = v.y;
            c[4 * k4 + 2] = v.z; c[4 * k4 + 3] = v.w;
        }
    } else {
        #pragma unroll
        for (int k = 0; k < SEG; k++) c[k] = (a + k < n) ? r[a + k] : 0.f;
    }
    // r[a-1] comes from the left neighbor lane (or a scalar load for lane 0)
    float fromLeft = __shfl_up_sync(0xffffffffu, c[SEG - 1], 1);
    if (lane == 0) fromLeft = (base > 0) ? r[base - 1] : 0.f;
    #pragma unroll
    for (int k = SEG - 1; k >= 1; k--) {   // descending: c[k-1] still raw r
        float rp = c[k - 1];
        float coef = (rp < 0.f) ? ag : alpha;
        c[k] = fmaf(coef * rp, rp, omega);
    }
    {
        float rp = fromLeft;
        float coef = (rp < 0.f) ? ag : alpha;
        c[0] = fmaf(coef * rp, rp, omega);
    }
    if (a == 0) c[0] = h0;   // inject h0: recurrence from Hin=0 then yields h[0]=h0

    // ---- pass 1: lane-local end value with zero carry ----
    float h = 0.f;
    #pragma unroll
    for (int k = 0; k < SEG; k++) h = fmaf(beta, h, c[k]);

    // ---- warp affine inclusive scan: (A,B) o (A',B') = (A*A', B + A*B') ----
    float A = m, B = h;
    #pragma unroll
    for (int d = 1; d < 32; d <<= 1) {
        float Bp = __shfl_up_sync(0xffffffffu, B, d);
        float Ap = __shfl_up_sync(0xffffffffu, A, d);
        if (lane >= d) { B = fmaf(A, Bp, B); A = A * Ap; }
    }
    float Bprev = __shfl_up_sync(0xffffffffu, B, 1);
    float Aprev = __shfl_up_sync(0xffffffffu, A, 1);
    float Hin = (lane == 0) ? Hw : fmaf(Aprev, Hw, Bprev);

    // ---- pass 2: serial with true carry, write h and sqrt(h) ----
    float* out_s = out;
    float* out_h = out + n;
    h = Hin;
    if (full) {
        float4* os = (float4*)(out_s + a);
        float4* oh = (float4*)(out_h + a);
        #pragma unroll
        for (int k4 = 0; k4 < SEG / 4; k4++) {
            float4 hv, sv;
            h = fmaf(beta, h, c[4 * k4 + 0]); hv.x = h; sv.x = sqrtf(h);
            h = fmaf(beta, h, c[4 * k4 + 1]); hv.y = h; sv.y = sqrtf(h);
            h = fmaf(beta, h, c[4 * k4 + 2]); hv.z = h; sv.z = sqrtf(h);
            h = fmaf(beta, h, c[4 * k4 + 3]); hv.w = h; sv.w = sqrtf(h);
            os[k4] = sv;
            oh[k4] = hv;
        }
    } else {
        #pragma unroll
        for (int k = 0; k < SEG; k++) {
            h = fmaf(beta, h, c[k]);
            if (a + k < n) { out_s[a + k] = sqrtf(h); out_h[a + k] = h; }
        }
    }
}

// ---------------------------------------------------------------------------
extern "C" void kernel_launch(void* const* d_in, const int* in_sizes, int n_in,
                              void* d_out, int out_size)
{
    const float* r       = (const float*)d_in[0];
    const float* p_omega = (const float*)d_in[1];
    const float* p_alpha = (const float*)d_in[2];
    const float* p_beta  = (const float*)d_in[3];
    const float* p_gamma = (const float*)d_in[4];
    const int n = in_sizes[0];

    k_reduce1<<<NPART, TPB>>>(r, n >> 2);
    k_reduce2<<<1, TPB>>>(n);

    const int nwarps = (n + CHUNK - 1) / CHUNK;
    const int blocks = (nwarps + (TPB / 32) - 1) / (TPB / 32);
    k_garch<<<blocks, TPB>>>(r, p_omega, p_alpha, p_beta, p_gamma,
                             (float*)d_out, n);
}

// round 2
// speedup vs baseline: 1.7005x; 1.7005x over previous
#include <cuda_runtime.h>
#include <math.h>

// GJR-GARCH(1,1):  h[t] = c[t] + beta*h[t-1],  h[0]=var(returns,ddof=1)
// c[t] = omega + (alpha + gamma*[r[t-1]<0]) * r[t-1]^2
// Output: [sqrt(h) | h], each N floats.
//
// Single fused pass: coalesced LDG.128 -> swizzled SMEM stage -> per-warp
// windowed carry (beta^256 truncation) + per-lane serial segments + warp
// affine scan -> h written back into SMEM in place -> coalesced STG.128.
// Variance partials are fused into the same pass; a tiny fixup kernel
// recomputes outputs [0,1024) once h0 is known (h0 decays out by t~250).

#define SEG       32
#define WPB       8
#define TPB       (WPB * 32)        // 256
#define CHUNK     (SEG * 32)        // 1024 elements per warp
#define BLK_ELEMS (WPB * CHUNK)     // 8192 elements per block
#define HALO      288               // >= 257 needed for 256-term window
#define SME       (HALO + BLK_ELEMS)
#define WWIN      256
#define NPART_MAX 32768
#define FIXN      1024

__device__ float g_ps[NPART_MAX];
__device__ float g_pq[NPART_MAX];
__device__ float g_h0;

// bank-rotation swizzle: element E lives at loc(E); row = E>>5 rotates columns
__device__ __forceinline__ int swz(int E) {
    return (E & ~31) | ((E + (E >> 5)) & 31);
}

// ---------------------------------------------------------------------------
// Main fused kernel
// ---------------------------------------------------------------------------
__global__ void __launch_bounds__(TPB) k_main(
    const float* __restrict__ r,
    const float* __restrict__ p_omega, const float* __restrict__ p_alpha,
    const float* __restrict__ p_beta,  const float* __restrict__ p_gamma,
    float* __restrict__ out, int n)
{
    __shared__ float sm[SME];
    __shared__ float rs[WPB], rq[WPB];

    const int tid  = threadIdx.x;
    const int w    = tid >> 5;
    const int lane = tid & 31;
    const int blockBase = blockIdx.x * BLK_ELEMS;

    const float omega = __ldg(p_omega);
    const float alpha = __ldg(p_alpha);
    const float beta  = __ldg(p_beta);
    const float gamma = __ldg(p_gamma);
    const float ag = alpha + gamma;

    // ---- coalesced load + swizzled stage + fused reduction partials ----
    float s = 0.f, q = 0.f;
    #pragma unroll
    for (int t = tid; t < SME / 4; t += TPB) {
        int gi = blockBase - HALO + 4 * t;
        float4 v;
        if (gi >= 0 && gi + 3 < n) {
            v = *(const float4*)(r + gi);
        } else {
            v.x = (gi + 0 >= 0 && gi + 0 < n) ? r[gi + 0] : 0.f;
            v.y = (gi + 1 >= 0 && gi + 1 < n) ? r[gi + 1] : 0.f;
            v.z = (gi + 2 >= 0 && gi + 2 < n) ? r[gi + 2] : 0.f;
            v.w = (gi + 3 >= 0 && gi + 3 < n) ? r[gi + 3] : 0.f;
        }
        int E = 4 * t;
        sm[swz(E + 0)] = v.x;
        sm[swz(E + 1)] = v.y;
        sm[swz(E + 2)] = v.z;
        sm[swz(E + 3)] = v.w;
        if (E >= HALO) {            // halo excluded (owned by previous block)
            s += (v.x + v.y) + (v.z + v.w);
            q = fmaf(v.x, v.x, q);
            q = fmaf(v.y, v.y, q);
            q = fmaf(v.z, v.z, q);
            q = fmaf(v.w, v.w, q);
        }
    }
    #pragma unroll
    for (int d = 16; d; d >>= 1) {
        s += __shfl_xor_sync(0xffffffffu, s, d);
        q += __shfl_xor_sync(0xffffffffu, q, d);
    }
    if (lane == 0) { rs[w] = s; rq[w] = q; }
    __syncthreads();                       // also publishes the staged tile
    if (tid == 0) {
        float S = 0.f, Q = 0.f;
        #pragma unroll
        for (int i = 0; i < WPB; i++) { S += rs[i]; Q += rq[i]; }
        g_ps[blockIdx.x] = S;
        g_pq[blockIdx.x] = Q;
    }

    const int  base   = blockBase + w * CHUNK;
    const bool active = (base < n);

    // beta^32 by squaring
    const float b2 = beta * beta, b4 = b2 * b2, b8 = b4 * b4, b16 = b8 * b8;
    const float m = b16 * b16;

    // ---- chunk carry-in Hw ~= h[base-1]: 256-term window, all from SMEM ----
    float Hw = 0.f;
    if (active && base > 0) {
        float bj = __powf(beta, (float)lane);     // beta^lane
        float P  = 0.f;
        const int Eb = HALO + w * CHUNK - 2 - lane;
        #pragma unroll
        for (int i = 0; i < WWIN / 32; i++) {     // term j = 32*i + lane
            float rp   = sm[swz(Eb - 32 * i)];
            float coef = (rp < 0.f) ? ag : alpha;
            P  = fmaf(bj, fmaf(coef * rp, rp, omega), P);
            bj *= m;
        }
        #pragma unroll
        for (int d = 16; d; d >>= 1) P += __shfl_xor_sync(0xffffffffu, P, d);
        Hw = P;
    }

    // ---- pass 1: per-lane end value, zero carry (conflict-free LDS) ----
    const int  E0 = HALO + w * CHUNK + lane * SEG;
    const float rv_first = sm[swz(E0 - 1)];   // r[a-1] (zero-halo for a==0)
    float h = 0.f;
    if (active) {
        float rp = rv_first;
        #pragma unroll
        for (int k = 0; k < SEG; k++) {
            float rv   = sm[swz(E0 + k)];
            float coef = (rp < 0.f) ? ag : alpha;
            h  = fmaf(beta, h, fmaf(coef * rp, rp, omega));
            rp = rv;
        }
    }

    // ---- warp affine inclusive scan: (A,B) o (A',B') = (A*A', B + A*B') ----
    float A = m, B = h;
    #pragma unroll
    for (int d = 1; d < 32; d <<= 1) {
        float Bp = __shfl_up_sync(0xffffffffu, B, d);
        float Ap = __shfl_up_sync(0xffffffffu, A, d);
        if (lane >= d) { B = fmaf(A, Bp, B); A *= Ap; }
    }
    float Bprev = __shfl_up_sync(0xffffffffu, B, 1);
    float Aprev = __shfl_up_sync(0xffffffffu, A, 1);
    float Hin = (lane == 0) ? Hw : fmaf(Aprev, Hw, Bprev);

    __syncthreads();   // all read-only uses of r tile done before overwrite

    // ---- pass 2: true carry, overwrite SMEM slots with h in place ----
    if (active) {
        float rp = rv_first;
        h = Hin;
        #pragma unroll
        for (int k = 0; k < SEG; k++) {
            int   L    = swz(E0 + k);
            float rv   = sm[L];                    // read r before overwrite
            float coef = (rp < 0.f) ? ag : alpha;
            h = fmaf(beta, h, fmaf(coef * rp, rp, omega));
            sm[L] = h;
            rp = rv;
        }
    }
    __syncwarp();

    // ---- writeback: conflict-free swizzled gather -> coalesced STG.128 ----
    if (active) {
        float* out_s = out;
        float* out_h = out + n;
        const bool al4 = ((n & 3) == 0);
        #pragma unroll
        for (int i = 0; i < 8; i++) {
            int e  = w * CHUNK + 128 * i + 4 * lane;
            int gi = blockBase + e;
            int Eh = HALO + e;
            if (al4 && gi + 3 < n) {
                float4 hv;
                hv.x = sm[swz(Eh + 0)];
                hv.y = sm[swz(Eh + 1)];
                hv.z = sm[swz(Eh + 2)];
                hv.w = sm[swz(Eh + 3)];
                *(float4*)(out_h + gi) = hv;
                float4 sv;
                sv.x = sqrtf(hv.x); sv.y = sqrtf(hv.y);
                sv.z = sqrtf(hv.z); sv.w = sqrtf(hv.w);
                *(float4*)(out_s + gi) = sv;
            } else {
                #pragma unroll
                for (int c = 0; c < 4; c++) {
                    if (gi + c < n) {
                        float hv = sm[swz(Eh + c)];
                        out_h[gi + c] = hv;
                        out_s[gi + c] = sqrtf(hv);
                    }
                }
            }
        }
    }
}

// ---------------------------------------------------------------------------
// Fold partials -> h0
// ---------------------------------------------------------------------------
__global__ void __launch_bounds__(256) k_h0(int nb, int n)
{
    __shared__ double ss[256], sq[256];
    double s = 0.0, q = 0.0;
    for (int i = threadIdx.x; i < nb; i += 256) {
        s += (double)g_ps[i];
        q += (double)g_pq[i];
    }
    ss[threadIdx.x] = s; sq[threadIdx.x] = q;
    __syncthreads();
    for (int ofs = 128; ofs; ofs >>= 1) {
        if (threadIdx.x < ofs) {
            ss[threadIdx.x] += ss[threadIdx.x + ofs];
            sq[threadIdx.x] += sq[threadIdx.x + ofs];
        }
        __syncthreads();
    }
    if (threadIdx.x == 0) {
        double S = ss[0], Q = sq[0];
        g_h0 = (float)((Q - S * S / (double)n) / (double)(n - 1));
    }
}

// ---------------------------------------------------------------------------
// Fixup: recompute outputs [0, FIXN) exactly from h0 (1 warp)
// ---------------------------------------------------------------------------
__global__ void __launch_bounds__(32) k_fix(
    const float* __restrict__ r,
    const float* __restrict__ p_omega, const float* __restrict__ p_alpha,
    const float* __restrict__ p_beta,  const float* __restrict__ p_gamma,
    float* __restrict__ out, int n)
{
    const int lane = threadIdx.x;
    const float omega = __ldg(p_omega);
    const float alpha = __ldg(p_alpha);
    const float beta  = __ldg(p_beta);
    const float gamma = __ldg(p_gamma);
    const float ag = alpha + gamma;
    const float h0 = g_h0;

    const float b2 = beta * beta, b4 = b2 * b2, b8 = b4 * b4, b16 = b8 * b8;
    const float m = b16 * b16;

    const int a = lane * SEG;

    // pass 1
    float h = 0.f;
    {
        float rp = (a > 0 && a - 1 < n) ? r[a - 1] : 0.f;
        #pragma unroll
        for (int k = 0; k < SEG; k++) {
            float rv = (a + k < n) ? r[a + k] : 0.f;
            float c;
            if (a + k == 0) c = h0;
            else {
                float coef = (rp < 0.f) ? ag : alpha;
                c = fmaf(coef * rp, rp, omega);
            }
            h  = fmaf(beta, h, c);
            rp = rv;
        }
    }

    // affine scan (carry-in is exactly 0 at t=0: h[0]=c[0]=h0)
    float A = m, B = h;
    #pragma unroll
    for (int d = 1; d < 32; d <<= 1) {
        float Bp = __shfl_up_sync(0xffffffffu, B, d);
        float Ap = __shfl_up_sync(0xffffffffu, A, d);
        if (lane >= d) { B = fmaf(A, Bp, B); A *= Ap; }
    }
    float Bprev = __shfl_up_sync(0xffffffffu, B, 1);
    float Hin = (lane == 0) ? 0.f : Bprev;

    // pass 2
    {
        float* out_s = out;
        float* out_h = out + n;
        float rp = (a > 0 && a - 1 < n) ? r[a - 1] : 0.f;
        h = Hin;
        #pragma unroll
        for (int k = 0; k < SEG; k++) {
            float rv = (a + k < n) ? r[a + k] : 0.f;
            float c;
            if (a + k == 0) c = h0;
            else {
                float coef = (rp < 0.f) ? ag : alpha;
                c = fmaf(coef * rp, rp, omega);
            }
            h = fmaf(beta, h, c);
            if (a + k < n) {
                out_h[a + k] = h;
                out_s[a + k] = sqrtf(h);
            }
            rp = rv;
        }
    }
}

// ---------------------------------------------------------------------------
extern "C" void kernel_launch(void* const* d_in, const int* in_sizes, int n_in,
                              void* d_out, int out_size)
{
    const float* r       = (const float*)d_in[0];
    const float* p_omega = (const float*)d_in[1];
    const float* p_alpha = (const float*)d_in[2];
    const float* p_beta  = (const float*)d_in[3];
    const float* p_gamma = (const float*)d_in[4];
    const int n = in_sizes[0];

    const int nb = (n + BLK_ELEMS - 1) / BLK_ELEMS;

    k_main<<<nb, TPB>>>(r, p_omega, p_alpha, p_beta, p_gamma, (float*)d_out, n);
    k_h0<<<1, 256>>>(nb, n);
    k_fix<<<1, 32>>>(r, p_omega, p_alpha, p_beta, p_gamma, (float*)d_out, n);
}

// round 3
// speedup vs baseline: 2.0080x; 1.1808x over previous
#include <cuda_runtime.h>
#include <math.h>

// GJR-GARCH(1,1):  h[t] = c[t] + beta*h[t-1],  h[0]=var(returns,ddof=1)
// c[t] = omega + (alpha + gamma*[r[t-1]<0]) * r[t-1]^2
// Output: [sqrt(h) | h], each N floats.
//
// Single kernel, no SMEM staging:
//  - warp owns a 2048-elem chunk; carry-in via 256-term beta window (beta^256~3e-19)
//  - 16 rounds of 128 contiguous elems; lane owns one float4 -> native LDG.128/STG.128
//  - per-round: 4-elem local affine prefix + 5-step warp affine scan + cross-round carry
//  - variance partials fused into the main loads; LAST block (atomic counter) folds
//    partials -> h0 and recomputes outputs [0,1024) (h0 influence decays by t~250)

#define WPB   8
#define TPB   (WPB * 32)        // 256
#define CHUNK 2048
#define NR    (CHUNK / 128)     // 16 rounds per warp-chunk
#define BLK   (WPB * CHUNK)     // 16384 elements per block
#define WWIN  256
#define NPART_MAX 32768
#define FULLMASK 0xffffffffu

__device__ float    g_ps[NPART_MAX];
__device__ float    g_pq[NPART_MAX];
__device__ unsigned g_done = 0;

__device__ __forceinline__ float sqrt_approx(float x) {
    float y; asm("sqrt.approx.f32 %0, %1;" : "=f"(y) : "f"(x)); return y;
}

__global__ void __launch_bounds__(TPB) k_all(
    const float* __restrict__ r,
    const float* __restrict__ p_omega, const float* __restrict__ p_alpha,
    const float* __restrict__ p_beta,  const float* __restrict__ p_gamma,
    float* __restrict__ out, int n)
{
    const int tid  = threadIdx.x;
    const int w    = tid >> 5;
    const int lane = tid & 31;
    const int base = blockIdx.x * BLK + w * CHUNK;

    const float omega = __ldg(p_omega);
    const float alpha = __ldg(p_alpha);
    const float beta  = __ldg(p_beta);
    const float gamma = __ldg(p_gamma);
    const float ag = alpha + gamma;

    const float b1 = beta;
    const float b2 = b1 * b1, b3 = b2 * b1, b4 = b2 * b2;
    const float b8 = b4 * b4, b16 = b8 * b8, b32 = b16 * b16;

    float s = 0.f, q = 0.f;

    if (base < n) {
        // ---- chunk carry-in Hc ~= h[base-1]: 256-term window (coalesced LDG) ----
        float Hc = 0.f;
        if (base > 0) {
            float bj = __powf(beta, (float)lane);          // beta^lane
            float P  = 0.f;
            const float* rb = r + base - 2 - lane;         // term j = 32*i + lane
            #pragma unroll
            for (int i = 0; i < WWIN / 32; i++) {
                float rp   = rb[-32 * i];
                float coef = (rp < 0.f) ? ag : alpha;
                P  = fmaf(bj, fmaf(coef * rp, rp, omega), P);
                bj *= b32;
            }
            #pragma unroll
            for (int d = 16; d; d >>= 1) P += __shfl_xor_sync(FULLMASK, P, d);
            Hc = P;
        }
        float rlast = (base > 0) ? __ldg(r + base - 1) : 0.f;

        if (base + CHUNK <= n && ((n & 3) == 0)) {
            // ================= fast path: full chunk, vectorized =================
            const float4* r4  = (const float4*)(r + base);
            float4*       oh4 = (float4*)(out + n + base);
            float4*       os4 = (float4*)(out + base);

            float4 v = r4[lane];
            #pragma unroll
            for (int j = 0; j < NR; j++) {
                float4 vn = make_float4(0.f, 0.f, 0.f, 0.f);
                if (j + 1 < NR) vn = r4[(j + 1) * 32 + lane];

                // fused variance partials
                s += (v.x + v.y) + (v.z + v.w);
                q = fmaf(v.x, v.x, q); q = fmaf(v.y, v.y, q);
                q = fmaf(v.z, v.z, q); q = fmaf(v.w, v.w, q);

                // previous element for lane's first slot
                float rp0 = __shfl_up_sync(FULLMASK, v.w, 1);
                if (lane == 0) rp0 = rlast;

                float c0, c1, c2, c3;
                { float t = rp0; float cf = (t < 0.f) ? ag : alpha; c0 = fmaf(cf * t, t, omega); }
                { float t = v.x; float cf = (t < 0.f) ? ag : alpha; c1 = fmaf(cf * t, t, omega); }
                { float t = v.y; float cf = (t < 0.f) ? ag : alpha; c2 = fmaf(cf * t, t, omega); }
                { float t = v.z; float cf = (t < 0.f) ? ag : alpha; c3 = fmaf(cf * t, t, omega); }

                // local affine prefix (zero carry)
                float p0 = c0;
                float p1 = fmaf(b1, p0, c1);
                float p2 = fmaf(b1, p1, c2);
                float p3 = fmaf(b1, p2, c3);

                // warp affine inclusive scan: (A,B) o (A',B') = (A*A', B + A*B')
                float A = b4, B = p3;
                #pragma unroll
                for (int d = 1; d < 32; d <<= 1) {
                    float Bp = __shfl_up_sync(FULLMASK, B, d);
                    float Ap = __shfl_up_sync(FULLMASK, A, d);
                    if (lane >= d) { B = fmaf(A, Bp, B); A *= Ap; }
                }
                float Bx = __shfl_up_sync(FULLMASK, B, 1);
                float Ax = __shfl_up_sync(FULLMASK, A, 1);
                float Hin = (lane == 0) ? Hc : fmaf(Ax, Hc, Bx);

                // apply carry (parallel, no serial chain)
                float h0v = fmaf(b1, Hin, p0);
                float h1v = fmaf(b2, Hin, p1);
                float h2v = fmaf(b3, Hin, p2);
                float h3v = fmaf(b4, Hin, p3);

                float4 hv = make_float4(h0v, h1v, h2v, h3v);
                float4 sv = make_float4(sqrt_approx(h0v), sqrt_approx(h1v),
                                        sqrt_approx(h2v), sqrt_approx(h3v));
                oh4[j * 32 + lane] = hv;
                os4[j * 32 + lane] = sv;

                Hc    = __shfl_sync(FULLMASK, h3v, 31);
                rlast = __shfl_sync(FULLMASK, v.w, 31);
                v = vn;
            }
        } else {
            // ================= guarded scalar path (partial chunk) =================
            #pragma unroll 1
            for (int j = 0; j < NR; j++) {
                int e0 = base + j * 128 + 4 * lane;
                float x0 = (e0 + 0 < n) ? r[e0 + 0] : 0.f;
                float x1 = (e0 + 1 < n) ? r[e0 + 1] : 0.f;
                float x2 = (e0 + 2 < n) ? r[e0 + 2] : 0.f;
                float x3 = (e0 + 3 < n) ? r[e0 + 3] : 0.f;

                s += (x0 + x1) + (x2 + x3);
                q = fmaf(x0, x0, q); q = fmaf(x1, x1, q);
                q = fmaf(x2, x2, q); q = fmaf(x3, x3, q);

                float rp0 = __shfl_up_sync(FULLMASK, x3, 1);
                if (lane == 0) rp0 = rlast;

                float c0, c1, c2, c3;
                { float t = rp0; float cf = (t < 0.f) ? ag : alpha; c0 = fmaf(cf * t, t, omega); }
                { float t = x0;  float cf = (t < 0.f) ? ag : alpha; c1 = fmaf(cf * t, t, omega); }
                { float t = x1;  float cf = (t < 0.f) ? ag : alpha; c2 = fmaf(cf * t, t, omega); }
                { float t = x2;  float cf = (t < 0.f) ? ag : alpha; c3 = fmaf(cf * t, t, omega); }

                float p0 = c0;
                float p1 = fmaf(b1, p0, c1);
                float p2 = fmaf(b1, p1, c2);
                float p3 = fmaf(b1, p2, c3);

                float A = b4, B = p3;
                #pragma unroll
                for (int d = 1; d < 32; d <<= 1) {
                    float Bp = __shfl_up_sync(FULLMASK, B, d);
                    float Ap = __shfl_up_sync(FULLMASK, A, d);
                    if (lane >= d) { B = fmaf(A, Bp, B); A *= Ap; }
                }
                float Bx = __shfl_up_sync(FULLMASK, B, 1);
                float Ax = __shfl_up_sync(FULLMASK, A, 1);
                float Hin = (lane == 0) ? Hc : fmaf(Ax, Hc, Bx);

                float h0v = fmaf(b1, Hin, p0);
                float h1v = fmaf(b2, Hin, p1);
                float h2v = fmaf(b3, Hin, p2);
                float h3v = fmaf(b4, Hin, p3);

                if (e0 + 0 < n) { out[n + e0 + 0] = h0v; out[e0 + 0] = sqrt_approx(h0v); }
                if (e0 + 1 < n) { out[n + e0 + 1] = h1v; out[e0 + 1] = sqrt_approx(h1v); }
                if (e0 + 2 < n) { out[n + e0 + 2] = h2v; out[e0 + 2] = sqrt_approx(h2v); }
                if (e0 + 3 < n) { out[n + e0 + 3] = h3v; out[e0 + 3] = sqrt_approx(h3v); }

                Hc    = __shfl_sync(FULLMASK, h3v, 31);
                rlast = __shfl_sync(FULLMASK, x3, 31);
            }
        }
    }

    // ---- block reduction of variance partials ----
    #pragma unroll
    for (int d = 16; d; d >>= 1) {
        s += __shfl_xor_sync(FULLMASK, s, d);
        q += __shfl_xor_sync(FULLMASK, q, d);
    }
    __shared__ float rs[WPB], rq[WPB];
    __shared__ bool  sLast;
    if (lane == 0) { rs[w] = s; rq[w] = q; }
    __syncthreads();
    if (tid == 0) {
        float S = 0.f, Q = 0.f;
        #pragma unroll
        for (int i = 0; i < WPB; i++) { S += rs[i]; Q += rq[i]; }
        g_ps[blockIdx.x] = S;
        g_pq[blockIdx.x] = Q;
    }
    __threadfence();
    __syncthreads();
    if (tid == 0) {
        unsigned c = atomicAdd(&g_done, 1u);
        sLast = (c == gridDim.x - 1);
    }
    __syncthreads();

    // ---- last block: fold partials -> h0, fixup outputs [0,1024) ----
    if (sLast) {
        __threadfence();
        __shared__ double ss[TPB], sq2[TPB];
        __shared__ float  sh0;
        const int nb = gridDim.x;
        double ds = 0.0, dq = 0.0;
        for (int i = tid; i < nb; i += TPB) {
            ds += (double)g_ps[i];
            dq += (double)g_pq[i];
        }
        ss[tid] = ds; sq2[tid] = dq;
        __syncthreads();
        for (int ofs = TPB / 2; ofs; ofs >>= 1) {
            if (tid < ofs) { ss[tid] += ss[tid + ofs]; sq2[tid] += sq2[tid + ofs]; }
            __syncthreads();
        }
        if (tid == 0) {
            double S = ss[0], Q = sq2[0];
            sh0 = (float)((Q - S * S / (double)n) / (double)(n - 1));
            g_done = 0;                       // reset for next graph replay
        }
        __syncthreads();

        if (tid < 32) {                       // 1 warp recomputes [0, 1024)
            const float h0 = sh0;
            const int a = lane * 32;

            // pass 1: lane end values, zero carry, c[0]=h0 injected
            float h = 0.f;
            {
                float rp = (a > 0 && a - 1 < n) ? r[a - 1] : 0.f;
                #pragma unroll
                for (int k = 0; k < 32; k++) {
                    float rv = (a + k < n) ? r[a + k] : 0.f;
                    float c;
                    if (a + k == 0) c = h0;
                    else { float cf = (rp < 0.f) ? ag : alpha; c = fmaf(cf * rp, rp, omega); }
                    h  = fmaf(beta, h, c);
                    rp = rv;
                }
            }
            // affine scan, m = beta^32
            float A = b32, B = h;
            #pragma unroll
            for (int d = 1; d < 32; d <<= 1) {
                float Bp = __shfl_up_sync(FULLMASK, B, d);
                float Ap = __shfl_up_sync(FULLMASK, A, d);
                if (lane >= d) { B = fmaf(A, Bp, B); A *= Ap; }
            }
            float Bprev = __shfl_up_sync(FULLMASK, B, 1);
            float Hin = (lane == 0) ? 0.f : Bprev;

            // pass 2: write
            {
                float rp = (a > 0 && a - 1 < n) ? r[a - 1] : 0.f;
                h = Hin;
                #pragma unroll
                for (int k = 0; k < 32; k++) {
                    float rv = (a + k < n) ? r[a + k] : 0.f;
                    float c;
                    if (a + k == 0) c = h0;
                    else { float cf = (rp < 0.f) ? ag : alpha; c = fmaf(cf * rp, rp, omega); }
                    h = fmaf(beta, h, c);
                    if (a + k < n) {
                        out[n + a + k] = h;
                        out[a + k]     = sqrt_approx(h);
                    }
                    rp = rv;
                }
            }
        }
    }
}

// ---------------------------------------------------------------------------
extern "C" void kernel_launch(void* const* d_in, const int* in_sizes, int n_in,
                              void* d_out, int out_size)
{
    const float* r       = (const float*)d_in[0];
    const float* p_omega = (const float*)d_in[1];
    const float* p_alpha = (const float*)d_in[2];
    const float* p_beta  = (const float*)d_in[3];
    const float* p_gamma = (const float*)d_in[4];
    const int n = in_sizes[0];

    const int nb = (n + BLK - 1) / BLK;
    k_all<<<nb, TPB>>>(r, p_omega, p_alpha, p_beta, p_gamma, (float*)d_out, n);
}

// round 5
// speedup vs baseline: 2.2106x; 1.1009x over previous
#include <cuda_runtime.h>
#include <math.h>

// GJR-GARCH(1,1):  h[t] = c[t] + beta*h[t-1],  h[0]=var(returns,ddof=1)
// c[t] = omega + (alpha + gamma*[r[t-1]<0]) * r[t-1]^2
// Output: [sqrt(h) | h], each N floats.
//
// Single kernel. Warp owns 2048 elems = 16 rounds of 128 (lane owns a float4).
// Rounds computed with 4-way ILP (groups of 4); cross-round dependence is only
// Hin(j) = T(j-1) + beta^128*Hin(j-1) (one fma per round). Warp scan is B-only
// Hillis-Steele with UNIFORM step multipliers m^d (m = beta^4): 5 shfl + 5 fma.
// Chunk carry-in via 128-term beta window. Variance partials fused; last block
// (atomic counter) folds h0 and recomputes outputs [0,1024).

#define WPB   8
#define TPB   (WPB * 32)        // 256
#define CHUNK 2048
#define BLK   (WPB * CHUNK)     // 16384 elements per block
#define NPART_MAX 32768
#define FULLMASK 0xffffffffu

__device__ float    g_ps[NPART_MAX];
__device__ float    g_pq[NPART_MAX];
__device__ unsigned g_done = 0;

__device__ __forceinline__ float sqrt_approx(float x) {
    float y; asm("sqrt.approx.f32 %0, %1;" : "=f"(y) : "f"(x)); return y;
}

// exact m^e for 0<=e<=31 from precomputed squarings
__device__ __forceinline__ float powk(float m1, float m2, float m4,
                                      float m8, float m16, int e) {
    float p = 1.f;
    if (e & 1)  p *= m1;
    if (e & 2)  p *= m2;
    if (e & 4)  p *= m4;
    if (e & 8)  p *= m8;
    if (e & 16) p *= m16;
    return p;
}

__global__ void __launch_bounds__(TPB) k_all(
    const float* __restrict__ r,
    const float* __restrict__ p_omega, const float* __restrict__ p_alpha,
    const float* __restrict__ p_beta,  const float* __restrict__ p_gamma,
    float* __restrict__ out, int n)
{
    const int tid  = threadIdx.x;
    const int w    = tid >> 5;
    const int lane = tid & 31;
    const int base = blockIdx.x * BLK + w * CHUNK;

    const float omega = __ldg(p_omega);
    const float alpha = __ldg(p_alpha);
    const float beta  = __ldg(p_beta);
    const float gamma = __ldg(p_gamma);
    const float ag = alpha + gamma;

    // powers of beta with power-of-two exponents (exact squarings)
    const float bp1 = beta;
    const float bp2 = bp1 * bp1, bp4 = bp2 * bp2, bp8 = bp4 * bp4;
    const float bp16 = bp8 * bp8, bp32 = bp16 * bp16;
    const float bp64 = bp32 * bp32, bp128 = bp64 * bp64;
    const float b3 = bp1 * bp2;

    // per-lane constants
    const float blane = powk(bp1, bp2, bp4, bp8, bp16, lane);   // beta^lane
    const float bl4   = powk(bp4, bp8, bp16, bp32, bp64, lane); // beta^(4*lane)

    float s = 0.f, q = 0.f;

    if (base < n) {
        // ---- chunk carry-in Hc ~= h[base-1]: 128-term window (coalesced) ----
        float Hc = 0.f;
        if (base > 0) {
            float bj = blane;
            float P  = 0.f;
            const float* rb = r + base - 2 - lane;       // term j = 32*i + lane
            #pragma unroll
            for (int i = 0; i < 4; i++) {
                float rp   = rb[-32 * i];
                float coef = (rp < 0.f) ? ag : alpha;
                P  = fmaf(bj, fmaf(coef * rp, rp, omega), P);
                bj *= bp32;
            }
            #pragma unroll
            for (int d = 16; d; d >>= 1) P += __shfl_xor_sync(FULLMASK, P, d);
            Hc = P;
        }
        float rlast = (base > 0) ? __ldg(r + base - 1) : 0.f;

        if (base + CHUNK <= n && ((n & 3) == 0)) {
            // =============== fast path: 4 groups x 4 ILP rounds ===============
            const float4* r4  = (const float4*)(r + base);
            float4*       oh4 = (float4*)(out + n + base);
            float4*       os4 = (float4*)(out + base);

            #pragma unroll
            for (int g = 0; g < 4; g++) {
                float4 v[4];
                #pragma unroll
                for (int i = 0; i < 4; i++) v[i] = r4[(4 * g + i) * 32 + lane];

                // fused variance partials
                #pragma unroll
                for (int i = 0; i < 4; i++) {
                    s += (v[i].x + v[i].y) + (v[i].z + v[i].w);
                    q = fmaf(v[i].x, v[i].x, q); q = fmaf(v[i].y, v[i].y, q);
                    q = fmaf(v[i].z, v[i].z, q); q = fmaf(v[i].w, v[i].w, q);
                }

                // previous-element for each lane's first slot, per round
                float rp0[4];
                #pragma unroll
                for (int i = 0; i < 4; i++) {
                    float su  = __shfl_up_sync(FULLMASK, v[i].w, 1);
                    float t31 = (i == 0) ? rlast
                                         : __shfl_sync(FULLMASK, v[i - 1].w, 31);
                    rp0[i] = (lane == 0) ? t31 : su;
                }
                rlast = __shfl_sync(FULLMASK, v[3].w, 31);

                // c-transform + local affine prefix (independent per round)
                float p0[4], p1[4], p2[4], p3[4];
                #pragma unroll
                for (int i = 0; i < 4; i++) {
                    float c0, c1, c2, c3;
                    { float t = rp0[i]; float cf = (t < 0.f) ? ag : alpha; c0 = fmaf(cf * t, t, omega); }
                    { float t = v[i].x; float cf = (t < 0.f) ? ag : alpha; c1 = fmaf(cf * t, t, omega); }
                    { float t = v[i].y; float cf = (t < 0.f) ? ag : alpha; c2 = fmaf(cf * t, t, omega); }
                    { float t = v[i].z; float cf = (t < 0.f) ? ag : alpha; c3 = fmaf(cf * t, t, omega); }
                    p0[i] = c0;
                    p1[i] = fmaf(bp1, c0, c1);
                    p2[i] = fmaf(bp1, p1[i], c2);
                    p3[i] = fmaf(bp1, p2[i], c3);
                }

                // 4 interleaved B-only warp scans; step d multiplier = m^d
                // (m = beta^4): bp4, bp8, bp16, bp32, bp64 — uniform constants
                float B[4];
                #pragma unroll
                for (int i = 0; i < 4; i++) B[i] = p3[i];
                {
                    float Bp[4];
                    #pragma unroll
                    for (int i = 0; i < 4; i++) Bp[i] = __shfl_up_sync(FULLMASK, B[i], 1);
                    #pragma unroll
                    for (int i = 0; i < 4; i++) if (lane >= 1) B[i] = fmaf(bp4, Bp[i], B[i]);
                    #pragma unroll
                    for (int i = 0; i < 4; i++) Bp[i] = __shfl_up_sync(FULLMASK, B[i], 2);
                    #pragma unroll
                    for (int i = 0; i < 4; i++) if (lane >= 2) B[i] = fmaf(bp8, Bp[i], B[i]);
                    #pragma unroll
                    for (int i = 0; i < 4; i++) Bp[i] = __shfl_up_sync(FULLMASK, B[i], 4);
                    #pragma unroll
                    for (int i = 0; i < 4; i++) if (lane >= 4) B[i] = fmaf(bp16, Bp[i], B[i]);
                    #pragma unroll
                    for (int i = 0; i < 4; i++) Bp[i] = __shfl_up_sync(FULLMASK, B[i], 8);
                    #pragma unroll
                    for (int i = 0; i < 4; i++) if (lane >= 8) B[i] = fmaf(bp32, Bp[i], B[i]);
                    #pragma unroll
                    for (int i = 0; i < 4; i++) Bp[i] = __shfl_up_sync(FULLMASK, B[i], 16);
                    #pragma unroll
                    for (int i = 0; i < 4; i++) if (lane >= 16) B[i] = fmaf(bp64, Bp[i], B[i]);
                }

                // exclusive scan value + per-round totals
                float Bx[4], T[4];
                #pragma unroll
                for (int i = 0; i < 4; i++) {
                    float bu = __shfl_up_sync(FULLMASK, B[i], 1);
                    Bx[i] = (lane == 0) ? 0.f : bu;
                    T[i]  = __shfl_sync(FULLMASK, B[i], 31);
                }

                // carry chain: one fma per round
                float Hin[4];
                Hin[0] = Hc;
                Hin[1] = fmaf(bp128, Hin[0], T[0]);
                Hin[2] = fmaf(bp128, Hin[1], T[1]);
                Hin[3] = fmaf(bp128, Hin[2], T[2]);
                Hc     = fmaf(bp128, Hin[3], T[3]);

                // apply carries + store
                #pragma unroll
                for (int i = 0; i < 4; i++) {
                    float Hl = fmaf(bl4, Hin[i], Bx[i]);   // h[a-1] for this lane
                    float h0v = fmaf(bp1, Hl, p0[i]);
                    float h1v = fmaf(bp2, Hl, p1[i]);
                    float h2v = fmaf(b3,  Hl, p2[i]);
                    float h3v = fmaf(bp4, Hl, p3[i]);
                    oh4[(4 * g + i) * 32 + lane] = make_float4(h0v, h1v, h2v, h3v);
                    os4[(4 * g + i) * 32 + lane] =
                        make_float4(sqrt_approx(h0v), sqrt_approx(h1v),
                                    sqrt_approx(h2v), sqrt_approx(h3v));
                }
            }
        } else {
            // =============== guarded scalar path (partial chunk) ===============
            #pragma unroll 1
            for (int j = 0; j < CHUNK / 128; j++) {
                int e0 = base + j * 128 + 4 * lane;
                float x0 = (e0 + 0 < n) ? r[e0 + 0] : 0.f;
                float x1 = (e0 + 1 < n) ? r[e0 + 1] : 0.f;
                float x2 = (e0 + 2 < n) ? r[e0 + 2] : 0.f;
                float x3 = (e0 + 3 < n) ? r[e0 + 3] : 0.f;

                s += (x0 + x1) + (x2 + x3);
                q = fmaf(x0, x0, q); q = fmaf(x1, x1, q);
                q = fmaf(x2, x2, q); q = fmaf(x3, x3, q);

                float rp0 = __shfl_up_sync(FULLMASK, x3, 1);
                if (lane == 0) rp0 = rlast;

                float c0, c1, c2, c3;
                { float t = rp0; float cf = (t < 0.f) ? ag : alpha; c0 = fmaf(cf * t, t, omega); }
                { float t = x0;  float cf = (t < 0.f) ? ag : alpha; c1 = fmaf(cf * t, t, omega); }
                { float t = x1;  float cf = (t < 0.f) ? ag : alpha; c2 = fmaf(cf * t, t, omega); }
                { float t = x2;  float cf = (t < 0.f) ? ag : alpha; c3 = fmaf(cf * t, t, omega); }

                float p0 = c0;
                float p1 = fmaf(bp1, p0, c1);
                float p2 = fmaf(bp1, p1, c2);
                float p3 = fmaf(bp1, p2, c3);

                // full (A,B) affine scan (robust for edge path)
                float A = bp4, B = p3;
                #pragma unroll
                for (int d = 1; d < 32; d <<= 1) {
                    float Bp = __shfl_up_sync(FULLMASK, B, d);
                    float Ap = __shfl_up_sync(FULLMASK, A, d);
                    if (lane >= d) { B = fmaf(A, Bp, B); A *= Ap; }
                }
                float Bu = __shfl_up_sync(FULLMASK, B, 1);
                float Bx = (lane == 0) ? 0.f : Bu;
                float Hl = fmaf(bl4, Hc, Bx);

                float h0v = fmaf(bp1, Hl, p0);
                float h1v = fmaf(bp2, Hl, p1);
                float h2v = fmaf(b3,  Hl, p2);
                float h3v = fmaf(bp4, Hl, p3);

                if (e0 + 0 < n) { out[n + e0 + 0] = h0v; out[e0 + 0] = sqrt_approx(h0v); }
                if (e0 + 1 < n) { out[n + e0 + 1] = h1v; out[e0 + 1] = sqrt_approx(h1v); }
                if (e0 + 2 < n) { out[n + e0 + 2] = h2v; out[e0 + 2] = sqrt_approx(h2v); }
                if (e0 + 3 < n) { out[n + e0 + 3] = h3v; out[e0 + 3] = sqrt_approx(h3v); }

                Hc    = __shfl_sync(FULLMASK, h3v, 31);
                rlast = __shfl_sync(FULLMASK, x3, 31);
            }
        }
    }

    // ---- block reduction of variance partials ----
    #pragma unroll
    for (int d = 16; d; d >>= 1) {
        s += __shfl_xor_sync(FULLMASK, s, d);
        q += __shfl_xor_sync(FULLMASK, q, d);
    }
    __shared__ float rs[WPB], rq[WPB];
    __shared__ bool  sLast;
    if (lane == 0) { rs[w] = s; rq[w] = q; }
    __syncthreads();
    if (tid == 0) {
        float S = 0.f, Q = 0.f;
        #pragma unroll
        for (int i = 0; i < WPB; i++) { S += rs[i]; Q += rq[i]; }
        g_ps[blockIdx.x] = S;
        g_pq[blockIdx.x] = Q;
    }
    __threadfence();
    __syncthreads();
    if (tid == 0) {
        unsigned c = atomicAdd(&g_done, 1u);
        sLast = (c == gridDim.x - 1);
    }
    __syncthreads();

    // ---- last block: fold partials -> h0, fixup outputs [0,1024) ----
    if (sLast) {
        __threadfence();
        __shared__ double ss[TPB], sq2[TPB];
        __shared__ float  sh0;
        const int nb = gridDim.x;
        double ds = 0.0, dq = 0.0;
        for (int i = tid; i < nb; i += TPB) {
            ds += (double)g_ps[i];
            dq += (double)g_pq[i];
        }
        ss[tid] = ds; sq2[tid] = dq;
        __syncthreads();
        for (int ofs = TPB / 2; ofs; ofs >>= 1) {
            if (tid < ofs) { ss[tid] += ss[tid + ofs]; sq2[tid] += sq2[tid + ofs]; }
            __syncthreads();
        }
        if (tid == 0) {
            double S = ss[0], Q = sq2[0];
            sh0 = (float)((Q - S * S / (double)n) / (double)(n - 1));
            g_done = 0;                       // reset for next graph replay
        }
        __syncthreads();

        if (tid < 32) {                       // 1 warp recomputes [0, 1024)
            const float h0 = sh0;
            const int a = lane * 32;

            float h = 0.f;
            {
                float rp = (a > 0 && a - 1 < n) ? r[a - 1] : 0.f;
                #pragma unroll
                for (int k = 0; k < 32; k++) {
                    float rv = (a + k < n) ? r[a + k] : 0.f;
                    float c;
                    if (a + k == 0) c = h0;
                    else { float cf = (rp < 0.f) ? ag : alpha; c = fmaf(cf * rp, rp, omega); }
                    h  = fmaf(beta, h, c);
                    rp = rv;
                }
            }
            float A = bp32, B = h;
            #pragma unroll
            for (int d = 1; d < 32; d <<= 1) {
                float Bp = __shfl_up_sync(FULLMASK, B, d);
                float Ap = __shfl_up_sync(FULLMASK, A, d);
                if (lane >= d) { B = fmaf(A, Bp, B); A *= Ap; }
            }
            float Bprev = __shfl_up_sync(FULLMASK, B, 1);
            float Hin = (lane == 0) ? 0.f : Bprev;

            {
                float rp = (a > 0 && a - 1 < n) ? r[a - 1] : 0.f;
                h = Hin;
                #pragma unroll
                for (int k = 0; k < 32; k++) {
                    float rv = (a + k < n) ? r[a + k] : 0.f;
                    float c;
                    if (a + k == 0) c = h0;
                    else { float cf = (rp < 0.f) ? ag : alpha; c = fmaf(cf * rp, rp, omega); }
                    h = fmaf(beta, h, c);
                    if (a + k < n) {
                        out[n + a + k] = h;
                        out[a + k]     = sqrt_approx(h);
                    }
                    rp = rv;
                }
            }
        }
    }
}

// ---------------------------------------------------------------------------
extern "C" void kernel_launch(void* const* d_in, const int* in_sizes, int n_in,
                              void* d_out, int out_size)
{
    const float* r       = (const float*)d_in[0];
    const float* p_omega = (const float*)d_in[1];
    const float* p_alpha = (const float*)d_in[2];
    const float* p_beta  = (const float*)d_in[3];
    const float* p_gamma = (const float*)d_in[4];
    const int n = in_sizes[0];

    const int nb = (n + BLK - 1) / BLK;
    k_all<<<nb, TPB>>>(r, p_omega, p_alpha, p_beta, p_gamma, (float*)d_out, n);
}